// round 12
// baseline (speedup 1.0000x reference)
#include <cuda_runtime.h>
#include <cuda_fp16.h>
#include <math.h>
#include <stdint.h>

#define B_DIM   8
#define HW_DIM  3136
#define C_DIM   256
#define NROWS   (B_DIM * HW_DIM)        // 25088
#define JT      64                      // j tile
#define NJT     (HW_DIM / JT)           // 49

// fused smem (bytes). X rows pitch 36 u4, T/S rows pitch 12 u4 (=4 mod 8 ->
// conflict-free LDS.128 fragment gathers). Xj and T double-buffered.
#define XP      36
#define TP      12
#define SM_XI   0                       // 64*36*16  = 36864
#define SM_XJ0  36864
#define SM_XJ1  73728
#define SM_TT0  110592                  // 256*12*16 = 49152
#define SM_TT1  159744
#define SM_SS   208896                  // 64*12*16  = 12288
#define SM_TOT  221184

// transform_mma smem: Wt 256 rows x 36 u4, X/staging 64x36 u4
#define TM_WT   0
#define TM_XT   147456
#define TM_TOT  184320

// device-global scratch (fp16)
__device__ __align__(16) unsigned short g_xn[(size_t)NROWS * C_DIM];          // xn [row][c]
__device__ __align__(16) unsigned short g_xh[(size_t)NROWS * C_DIM];          // raw x fp16
__device__ __align__(16) unsigned short g_wt[(size_t)C_DIM * C_DIM];          // W^T [c][k]
__device__ __align__(16) unsigned short g_tt[(size_t)B_DIM * C_DIM * HW_DIM]; // t  [b][c][hw]

__device__ __forceinline__ uint32_t h2pack(float a, float b) {
    __half2 h = __floats2half2_rn(a, b);
    return *reinterpret_cast<uint32_t*>(&h);
}
__device__ __forceinline__ uint32_t smem_u32(const void* p) {
    uint32_t a;
    asm("{ .reg .u64 t; cvta.to.shared.u64 t, %1; cvt.u32.u64 %0, t; }" : "=r"(a) : "l"(p));
    return a;
}
__device__ __forceinline__ void cp16(uint32_t dst, const void* src) {
    asm volatile("{ .reg .u64 g; cvta.to.global.u64 g, %1;"
                 " cp.async.cg.shared.global [%0], [g], 16; }" :: "r"(dst), "l"(src));
}
#define CP_COMMIT() asm volatile("cp.async.commit_group;" ::: "memory")
#define CP_WAIT0()  asm volatile("cp.async.wait_group 0;" ::: "memory")
#define CP_WAIT1()  asm volatile("cp.async.wait_group 1;" ::: "memory")

__device__ __forceinline__ void mma16(float* d, uint32_t a0, uint32_t a1,
                                      uint32_t a2, uint32_t a3,
                                      uint32_t b0, uint32_t b1) {
    asm volatile(
        "mma.sync.aligned.m16n8k16.row.col.f32.f16.f16.f32 "
        "{%0,%1,%2,%3}, {%4,%5,%6,%7}, {%8,%9}, {%0,%1,%2,%3};"
        : "+f"(d[0]), "+f"(d[1]), "+f"(d[2]), "+f"(d[3])
        : "r"(a0), "r"(a1), "r"(a2), "r"(a3), "r"(b0), "r"(b1));
}

// ---------------------------------------------------------------------------
// Kernel A: L2 normalize -> g_xn (fp16) and raw x -> g_xh (fp16)
// ---------------------------------------------------------------------------
__global__ void norm_kernel(const float* __restrict__ x) {
    int row  = blockIdx.x * 8 + threadIdx.y;
    int lane = threadIdx.x;
    const float4* xr = reinterpret_cast<const float4*>(x) + (size_t)row * (C_DIM / 4);
    float4 v0 = xr[lane];
    float4 v1 = xr[lane + 32];
    float s = v0.x*v0.x + v0.y*v0.y + v0.z*v0.z + v0.w*v0.w
            + v1.x*v1.x + v1.y*v1.y + v1.z*v1.z + v1.w*v1.w;
#pragma unroll
    for (int off = 16; off > 0; off >>= 1) s += __shfl_xor_sync(0xffffffffu, s, off);
    float inv = rsqrtf(fmaxf(s, 1e-12f));
    uint2* oh = reinterpret_cast<uint2*>(g_xh) + (size_t)row * (C_DIM / 4);
    oh[lane]      = make_uint2(h2pack(v0.x, v0.y), h2pack(v0.z, v0.w));
    oh[lane + 32] = make_uint2(h2pack(v1.x, v1.y), h2pack(v1.z, v1.w));
    uint2* o = reinterpret_cast<uint2*>(g_xn) + (size_t)row * (C_DIM / 4);
    o[lane]      = make_uint2(h2pack(v0.x*inv, v0.y*inv), h2pack(v0.z*inv, v0.w*inv));
    o[lane + 32] = make_uint2(h2pack(v1.x*inv, v1.y*inv), h2pack(v1.z*inv, v1.w*inv));
}

// ---------------------------------------------------------------------------
// Kernel A2: W^T -> g_wt[c][k] fp16
// ---------------------------------------------------------------------------
__global__ void wt_kernel(const float* __restrict__ W) {
    int c = blockIdx.x, k = threadIdx.x;
    g_wt[(size_t)c * C_DIM + k] = __half_as_ushort(__float2half_rn(W[(size_t)k * C_DIM + c]));
}

// ---------------------------------------------------------------------------
// Kernel B: t = x @ W on fp16 tensor cores; stored transposed: g_tt[b][c][hw]
// ---------------------------------------------------------------------------
__global__ __launch_bounds__(256)
void transform_mma() {
    extern __shared__ char smem[];
    uint32_t sbase = smem_u32(smem);
    const uint4* Wt4 = reinterpret_cast<const uint4*>(smem + TM_WT);
    const uint4* X4  = reinterpret_cast<const uint4*>(smem + TM_XT);
    __half*      stg = reinterpret_cast<__half*>(smem + TM_XT);

    int row0 = blockIdx.x * 64;
    int tid = threadIdx.x, w = tid >> 5, lane = tid & 31;
    int gid = lane >> 2, tig = lane & 3;
    int wr = w & 1, wn = w >> 1;

#pragma unroll
    for (int q = 0; q < 32; q++) {
        int idx = tid + q * 256, r = idx >> 5, c4 = idx & 31;
        cp16(sbase + TM_WT + (uint32_t)(r * XP + c4) * 16,
             g_wt + (size_t)r * C_DIM + c4 * 8);
    }
#pragma unroll
    for (int q = 0; q < 8; q++) {
        int idx = tid + q * 256, r = idx >> 5, c4 = idx & 31;
        cp16(sbase + TM_XT + (uint32_t)(r * XP + c4) * 16,
             g_xh + (size_t)(row0 + r) * C_DIM + c4 * 8);
    }
    CP_COMMIT(); CP_WAIT0();
    __syncthreads();

    float yacc[2][8][4];
#pragma unroll
    for (int mb = 0; mb < 2; mb++)
#pragma unroll
        for (int nt = 0; nt < 8; nt++)
#pragma unroll
            for (int q = 0; q < 4; q++) yacc[mb][nt][q] = 0.f;

#pragma unroll
    for (int kc = 0; kc < 8; kc++) {
        uint4 Ag[2], Ag8[2];
#pragma unroll
        for (int mb = 0; mb < 2; mb++) {
            int r1 = 32 * wr + 16 * mb + gid;
            Ag[mb]  = X4[r1 * XP + 4 * kc + tig];
            Ag8[mb] = X4[(r1 + 8) * XP + 4 * kc + tig];
        }
#pragma unroll
        for (int nt = 0; nt < 8; nt++) {
            int c = 64 * wn + 8 * nt + gid;
            uint4 Bv = Wt4[c * XP + 4 * kc + tig];
            const uint32_t* bn = reinterpret_cast<const uint32_t*>(&Bv);
#pragma unroll
            for (int ss = 0; ss < 2; ss++)
#pragma unroll
                for (int mb = 0; mb < 2; mb++) {
                    const uint32_t* ag  = reinterpret_cast<const uint32_t*>(&Ag[mb]);
                    const uint32_t* ag8 = reinterpret_cast<const uint32_t*>(&Ag8[mb]);
                    mma16(yacc[mb][nt], ag[2*ss], ag8[2*ss], ag[2*ss+1], ag8[2*ss+1],
                          bn[2*ss], bn[2*ss+1]);
                }
        }
    }
    __syncthreads();

#pragma unroll
    for (int mb = 0; mb < 2; mb++)
#pragma unroll
        for (int nt = 0; nt < 8; nt++) {
            int r1 = 32 * wr + 16 * mb + gid;
            int c  = 64 * wn + 8 * nt + 2 * tig;
            stg[c * 72 + r1]           = __float2half_rn(yacc[mb][nt][0]);
            stg[(c + 1) * 72 + r1]     = __float2half_rn(yacc[mb][nt][1]);
            stg[c * 72 + r1 + 8]       = __float2half_rn(yacc[mb][nt][2]);
            stg[(c + 1) * 72 + r1 + 8] = __float2half_rn(yacc[mb][nt][3]);
        }
    __syncthreads();

    int bb = row0 / HW_DIM, hw0 = row0 - bb * HW_DIM;
#pragma unroll
    for (int p = 0; p < 4; p++) {
        int c = p * 64 + (tid >> 2), ch = tid & 3;
        uint4 v  = *reinterpret_cast<const uint4*>(&stg[c * 72 + ch * 16]);
        uint4 v2 = *reinterpret_cast<const uint4*>(&stg[c * 72 + ch * 16 + 8]);
        *reinterpret_cast<uint4*>(
            &g_tt[((size_t)bb * C_DIM + c) * HW_DIM + hw0 + ch * 16]) = v;
        *reinterpret_cast<uint4*>(
            &g_tt[((size_t)bb * C_DIM + c) * HW_DIM + hw0 + ch * 16 + 8]) = v2;
    }
}

// ---------------------------------------------------------------------------
// Kernel C: fused pass, mma.sync fp16, 512 threads (16 warps) per CTA for
// latency hiding (4 warps/scheduler). Same 64-row i-tile & smem as before.
//   ph1: warp grid 4x4, warp tile 16x16 (sacc 8 regs)
//   ph2: warp grid 2x8, warp tile 32x32 (yacc 32 regs)
// ---------------------------------------------------------------------------
__global__ __launch_bounds__(512)
void ppm_fused(float* __restrict__ y) {
    extern __shared__ char smem[];
    uint32_t sbase = smem_u32(smem);
    const uint4* Xi4 = reinterpret_cast<const uint4*>(smem + SM_XI);
    uint32_t*    sS  = reinterpret_cast<uint32_t*>(smem + SM_SS);
    const uint4* S4  = reinterpret_cast<const uint4*>(smem + SM_SS);

    int b  = blockIdx.y;
    int i0 = blockIdx.x * JT;
    const unsigned short* Xg = g_xn + (size_t)b * HW_DIM * C_DIM;
    const unsigned short* Tg = g_tt + (size_t)b * C_DIM * HW_DIM;

    int tid = threadIdx.x, w = tid >> 5, lane = tid & 31;
    int gid = lane >> 2, tig = lane & 3;
    int wm1 = w & 3, wn1 = w >> 2;     // phase-1 warp grid 4x4
    int wm2 = w & 1, wn2 = w >> 1;     // phase-2 warp grid 2x8

    const uint32_t xjOff[2] = {SM_XJ0, SM_XJ1};
    const uint32_t ttOff[2] = {SM_TT0, SM_TT1};

    auto loadX = [&](int r0, uint32_t dstb) {
#pragma unroll
        for (int q = 0; q < 4; q++) {
            int idx = tid + q * 512, r = idx >> 5, c4 = idx & 31;
            cp16(sbase + dstb + (uint32_t)(r * XP + c4) * 16,
                 Xg + (size_t)(r0 + r) * C_DIM + c4 * 8);
        }
    };
    auto loadT = [&](int j0, uint32_t dstb) {
#pragma unroll
        for (int q = 0; q < 4; q++) {
            int idx = tid + q * 512, c = idx >> 3, k4 = idx & 7;
            cp16(sbase + dstb + (uint32_t)(c * TP + k4) * 16,
                 Tg + (size_t)c * HW_DIM + j0 + k4 * 8);
        }
    };

    loadX(i0, SM_XI);
    loadX(0, SM_XJ0);
    loadT(0, SM_TT0);
    CP_COMMIT();
    loadX(JT, SM_XJ1);
    loadT(JT, SM_TT1);
    CP_COMMIT();

    float yacc[2][4][4];
#pragma unroll
    for (int mb = 0; mb < 2; mb++)
#pragma unroll
        for (int nt = 0; nt < 4; nt++)
#pragma unroll
            for (int q = 0; q < 4; q++) yacc[mb][nt][q] = 0.f;

    for (int j = 0; j < NJT; j++) {
        int s = j & 1;
        if (j == NJT - 1) CP_WAIT0(); else CP_WAIT1();
        __syncthreads();
        const uint4* Xj4 = reinterpret_cast<const uint4*>(smem + xjOff[s]);
        const uint4* T4  = reinterpret_cast<const uint4*>(smem + ttOff[s]);

        // ---- phase 1: S(16x16/warp) = Xi @ Xj^T over K=256
        float sacc[2][4] = {};
        int r1a = 16 * wm1 + gid;
#pragma unroll
        for (int kc = 0; kc < 8; kc++) {
            uint4 Ag  = Xi4[r1a * XP + 4 * kc + tig];
            uint4 Ag8 = Xi4[(r1a + 8) * XP + 4 * kc + tig];
            uint4 Bn[2];
#pragma unroll
            for (int nb = 0; nb < 2; nb++) {
                int n1 = 16 * wn1 + 8 * nb + gid;
                Bn[nb] = Xj4[n1 * XP + 4 * kc + tig];
            }
            const uint32_t* ag  = reinterpret_cast<const uint32_t*>(&Ag);
            const uint32_t* ag8 = reinterpret_cast<const uint32_t*>(&Ag8);
#pragma unroll
            for (int ss = 0; ss < 2; ss++)
#pragma unroll
                for (int nb = 0; nb < 2; nb++) {
                    const uint32_t* bn = reinterpret_cast<const uint32_t*>(&Bn[nb]);
                    mma16(sacc[nb], ag[2*ss], ag8[2*ss], ag[2*ss+1], ag8[2*ss+1],
                          bn[2*ss], bn[2*ss+1]);
                }
        }
        // relu^2 -> sS
#pragma unroll
        for (int nb = 0; nb < 2; nb++) {
            int cw = 8 * wn1 + 4 * nb + tig;
            float v0 = fmaxf(sacc[nb][0], 0.f), v1 = fmaxf(sacc[nb][1], 0.f);
            float v2 = fmaxf(sacc[nb][2], 0.f), v3 = fmaxf(sacc[nb][3], 0.f);
            sS[r1a * (TP * 4) + cw]       = h2pack(v0 * v0, v1 * v1);
            sS[(r1a + 8) * (TP * 4) + cw] = h2pack(v2 * v2, v3 * v3);
        }
        __syncthreads();

        if (j + 2 < NJT) loadX((j + 2) * JT, xjOff[s]);

        // ---- phase 2: Y(32x32/warp) += S @ T over K=64
#pragma unroll
        for (int kc = 0; kc < 2; kc++) {
            uint4 Ag[2], Ag8[2];
#pragma unroll
            for (int mb = 0; mb < 2; mb++) {
                int r1 = 32 * wm2 + 16 * mb + gid;
                Ag[mb]  = S4[r1 * TP + 4 * kc + tig];
                Ag8[mb] = S4[(r1 + 8) * TP + 4 * kc + tig];
            }
#pragma unroll
            for (int nt = 0; nt < 4; nt++) {
                int c = 32 * wn2 + 8 * nt + gid;
                uint4 Bv = T4[c * TP + 4 * kc + tig];
                const uint32_t* bn = reinterpret_cast<const uint32_t*>(&Bv);
#pragma unroll
                for (int ss = 0; ss < 2; ss++)
#pragma unroll
                    for (int mb = 0; mb < 2; mb++) {
                        const uint32_t* ag  = reinterpret_cast<const uint32_t*>(&Ag[mb]);
                        const uint32_t* ag8 = reinterpret_cast<const uint32_t*>(&Ag8[mb]);
                        mma16(yacc[mb][nt], ag[2*ss], ag8[2*ss], ag[2*ss+1], ag8[2*ss+1],
                              bn[2*ss], bn[2*ss+1]);
                    }
            }
        }
        __syncthreads();

        if (j + 2 < NJT) { loadT((j + 2) * JT, ttOff[s]); CP_COMMIT(); }
    }

    // epilogue
    float* Yb = y + ((size_t)b * HW_DIM + i0) * C_DIM;
#pragma unroll
    for (int mb = 0; mb < 2; mb++) {
        int r1 = 32 * wm2 + 16 * mb + gid;
#pragma unroll
        for (int nt = 0; nt < 4; nt++) {
            int c = 32 * wn2 + 8 * nt + 2 * tig;
            *reinterpret_cast<float2*>(&Yb[(size_t)r1 * C_DIM + c]) =
                make_float2(yacc[mb][nt][0], yacc[mb][nt][1]);
            *reinterpret_cast<float2*>(&Yb[(size_t)(r1 + 8) * C_DIM + c]) =
                make_float2(yacc[mb][nt][2], yacc[mb][nt][3]);
        }
    }
}

// ---------------------------------------------------------------------------
extern "C" void kernel_launch(void* const* d_in, const int* in_sizes, int n_in,
                              void* d_out, int out_size) {
    const float* x = (const float*)d_in[0];
    const float* W = (const float*)d_in[1];
    float* y = (float*)d_out;
    (void)in_sizes; (void)n_in; (void)out_size;

    norm_kernel<<<NROWS / 8, dim3(32, 8)>>>(x);
    wt_kernel<<<C_DIM, C_DIM>>>(W);

    cudaFuncSetAttribute(transform_mma, cudaFuncAttributeMaxDynamicSharedMemorySize, TM_TOT);
    transform_mma<<<NROWS / 64, 256, TM_TOT>>>();

    cudaFuncSetAttribute(ppm_fused, cudaFuncAttributeMaxDynamicSharedMemorySize, SM_TOT);
    ppm_fused<<<dim3(HW_DIM / JT, B_DIM), 512, SM_TOT>>>(y);
}